// round 2
// baseline (speedup 1.0000x reference)
#include <cuda_runtime.h>
#include <math.h>

#define B_ 8
#define S_ 256
#define V_ 32000
#define E_ 512
#define H_ 1024
#define G_ 3072      // 3H
#define T_ 2048      // B*S
#define F_ 1536      // H+E
#define NT_ 250      // V/128 score tiles per row
#define GRU_CTAS 128

// ---------------- scratch (static device globals; no allocation) ----------------
__device__ float g_Wpack[(size_t)GRU_CTAS * 1024 * 32];  // per-CTA packed W_hh [c][k][g24(pad32)]
__device__ float g_feat[(size_t)T_ * F_];                // [t][ ctx(1024) | emb(512) ]
__device__ float g_gx[(size_t)T_ * G_];                  // input gates
__device__ float g_logits[(size_t)T_ * E_];
__device__ float2 g_part[(size_t)T_ * NT_];              // per (row, vtile): (max, sumexp)
__device__ float g_lse[T_];
__device__ float g_hbuf[2 * H_ * B_];                    // ping-pong hidden state [k][b]
__device__ unsigned int g_cnt[S_];                       // per-step barrier counters

// ---------------- K0: pack W_hh per GRU CTA + zero barrier counters ----------------
// CTA c owns j in [c*8, c*8+8). g24 = gate*8 + jj -> row g = gate*1024 + c*8 + jj.
__global__ void pack_kernel(const float* __restrict__ W_hh) {
    int c = blockIdx.x, tid = threadIdx.x;
    if (c == 0 && tid < S_) g_cnt[tid] = 0u;   // must be zero every launch (graph replay)
    for (int idx = tid; idx < 1024 * 32; idx += 256) {
        int k = idx >> 5, g24 = idx & 31;
        float v = 0.f;
        if (g24 < 24) {
            int gate = g24 >> 3, jj = g24 & 7;
            int g = gate * H_ + c * 8 + jj;
            v = W_hh[(size_t)g * H_ + k];
        }
        g_Wpack[(size_t)c * 32768 + idx] = v;
    }
}

// ---------------- K1: embedding gather into feat[:, H:] ----------------
__global__ void embed_kernel(const int* __restrict__ x, const float* __restrict__ emb_W) {
    int t = blockIdx.x, tid = threadIdx.x;  // 128 threads: 128 float4 = 512 floats
    int tok = x[t];
    const float4* src = (const float4*)(emb_W + (size_t)tok * E_);
    float4* dst = (float4*)(g_feat + (size_t)t * F_ + H_);
    dst[tid] = src[tid];
}

// ---------------- generic C = A @ B^T tiled GEMM (128x128x16, 8x8/thread) ----------------
// EPI 0: +bias, store. EPI 1: tanh(+bias), store. EPI 2: store + per-tile (max,sumexp) partials.
template <int EPI>
__global__ void __launch_bounds__(256) gemm_kernel(
    const float* __restrict__ A, int lda,
    const float* __restrict__ Bm, int ldb,
    const float* __restrict__ bias,
    float* __restrict__ C, int ldc,
    int K, float2* __restrict__ part)
{
    __shared__ float As[16 * 128];
    __shared__ float Bs[16 * 128];
    const int tid = threadIdx.x;
    const int tx = tid & 15, ty = tid >> 4;
    const int m0 = blockIdx.y * 128, n0 = blockIdx.x * 128;

    float acc[8][8];
#pragma unroll
    for (int i = 0; i < 8; ++i)
#pragma unroll
        for (int j = 0; j < 8; ++j) acc[i][j] = 0.f;

    for (int k0 = 0; k0 < K; k0 += 16) {
#pragma unroll
        for (int r = 0; r < 2; ++r) {
            int idx = tid + r * 256;
            int rr = idx >> 2, q = idx & 3;
            float4 va = *(const float4*)(A + (size_t)(m0 + rr) * lda + k0 + q * 4);
            As[(q * 4 + 0) * 128 + rr] = va.x;
            As[(q * 4 + 1) * 128 + rr] = va.y;
            As[(q * 4 + 2) * 128 + rr] = va.z;
            As[(q * 4 + 3) * 128 + rr] = va.w;
            float4 vb = *(const float4*)(Bm + (size_t)(n0 + rr) * ldb + k0 + q * 4);
            Bs[(q * 4 + 0) * 128 + rr] = vb.x;
            Bs[(q * 4 + 1) * 128 + rr] = vb.y;
            Bs[(q * 4 + 2) * 128 + rr] = vb.z;
            Bs[(q * 4 + 3) * 128 + rr] = vb.w;
        }
        __syncthreads();
#pragma unroll
        for (int kk = 0; kk < 16; ++kk) {
            float a[8], b[8];
            *(float4*)(a)     = *(const float4*)(As + kk * 128 + ty * 8);
            *(float4*)(a + 4) = *(const float4*)(As + kk * 128 + ty * 8 + 4);
            *(float4*)(b)     = *(const float4*)(Bs + kk * 128 + tx * 8);
            *(float4*)(b + 4) = *(const float4*)(Bs + kk * 128 + tx * 8 + 4);
#pragma unroll
            for (int i = 0; i < 8; ++i)
#pragma unroll
                for (int j = 0; j < 8; ++j) acc[i][j] += a[i] * b[j];
        }
        __syncthreads();
    }

    if (EPI == 0 || EPI == 1) {
        float bn[8];
#pragma unroll
        for (int j = 0; j < 8; ++j) bn[j] = bias[n0 + tx * 8 + j];
#pragma unroll
        for (int i = 0; i < 8; ++i) {
            float* cp = C + (size_t)(m0 + ty * 8 + i) * ldc + n0 + tx * 8;
#pragma unroll
            for (int j4 = 0; j4 < 8; j4 += 4) {
                float4 v;
                v.x = acc[i][j4 + 0] + bn[j4 + 0];
                v.y = acc[i][j4 + 1] + bn[j4 + 1];
                v.z = acc[i][j4 + 2] + bn[j4 + 2];
                v.w = acc[i][j4 + 3] + bn[j4 + 3];
                if (EPI == 1) { v.x = tanhf(v.x); v.y = tanhf(v.y); v.z = tanhf(v.z); v.w = tanhf(v.w); }
                *(float4*)(cp + j4) = v;
            }
        }
    } else {
        // store scores
#pragma unroll
        for (int i = 0; i < 8; ++i) {
            float* cp = C + (size_t)(m0 + ty * 8 + i) * ldc + n0 + tx * 8;
#pragma unroll
            for (int j4 = 0; j4 < 8; j4 += 4) {
                float4 v = make_float4(acc[i][j4], acc[i][j4 + 1], acc[i][j4 + 2], acc[i][j4 + 3]);
                *(float4*)(cp + j4) = v;
            }
        }
        // per-row max over this 128-wide tile
        float* red = As;     // reuse: [128][16]
        float* rms = Bs;     // reuse: [128]
#pragma unroll
        for (int i = 0; i < 8; ++i) {
            float m = acc[i][0];
#pragma unroll
            for (int j = 1; j < 8; ++j) m = fmaxf(m, acc[i][j]);
            red[(ty * 8 + i) * 16 + tx] = m;
        }
        __syncthreads();
        if (tid < 128) {
            float m = -1e30f;
#pragma unroll
            for (int t = 0; t < 16; ++t) m = fmaxf(m, red[tid * 16 + t]);
            rms[tid] = m;
        }
        __syncthreads();
#pragma unroll
        for (int i = 0; i < 8; ++i) {
            float rm = rms[ty * 8 + i];
            float s = 0.f;
#pragma unroll
            for (int j = 0; j < 8; ++j) s += __expf(acc[i][j] - rm);
            red[(ty * 8 + i) * 16 + tx] = s;
        }
        __syncthreads();
        if (tid < 128) {
            float s = 0.f;
#pragma unroll
            for (int t = 0; t < 16; ++t) s += red[tid * 16 + t];
            part[(size_t)(m0 + tid) * NT_ + blockIdx.x] = make_float2(rms[tid], s);
        }
    }
}

// ---------------- K3: persistent GRU (128 CTAs, 1 grid barrier / step) ----------------
__global__ void __launch_bounds__(256, 1) gru_kernel(const int* __restrict__ x,
                                                     const float* __restrict__ b_hh) {
    __shared__ float h_s[H_ * B_];        // [k][b]  32 KB
    __shared__ float red[24 * 8 * 8];     // [g24][kc][b]
    __shared__ float gh_s[24 * 8];        // [g24][b]
    const int c = blockIdx.x, tid = threadIdx.x;
    const int j0 = c * 8;
    const int g24 = tid % 24, kc = tid / 24;   // valid for tid < 192

    for (int s = 0; s < S_; ++s) {
        const int p = s & 1;
        if (s == 0) {
            for (int i = tid; i < H_ * B_; i += 256) h_s[i] = 0.f;
        } else {
            const float4* src = (const float4*)(g_hbuf + p * H_ * B_);
            float4* dst = (float4*)h_s;
#pragma unroll
            for (int r = 0; r < 8; ++r) dst[tid + r * 256] = __ldcg(src + tid + r * 256);
        }
        __syncthreads();

        if (tid < 192) {
            float a0 = 0, a1 = 0, a2 = 0, a3 = 0, a4 = 0, a5 = 0, a6 = 0, a7 = 0;
            const float* wp = g_Wpack + ((size_t)c * 1024 + kc * 128) * 32 + g24;
            const float4* h4 = (const float4*)h_s + kc * 128 * 2;
#pragma unroll 4
            for (int k = 0; k < 128; ++k) {
                float w = wp[k * 32];
                float4 ha = h4[2 * k], hb = h4[2 * k + 1];
                a0 += w * ha.x; a1 += w * ha.y; a2 += w * ha.z; a3 += w * ha.w;
                a4 += w * hb.x; a5 += w * hb.y; a6 += w * hb.z; a7 += w * hb.w;
            }
            float* rp = red + (g24 * 8 + kc) * 8;
            rp[0] = a0; rp[1] = a1; rp[2] = a2; rp[3] = a3;
            rp[4] = a4; rp[5] = a5; rp[6] = a6; rp[7] = a7;
        }
        __syncthreads();
        if (tid < 192) {
            int gg = tid % 24, b = tid / 24;
            float v = 0.f;
#pragma unroll
            for (int q = 0; q < 8; ++q) v += red[(gg * 8 + q) * 8 + b];
            gh_s[gg * 8 + b] = v;
        }
        __syncthreads();
        if (tid < 64) {
            int jj = tid >> 3, b = tid & 7;
            int j = j0 + jj;
            int tix = b * S_ + s;
            const float* gxr = g_gx + (size_t)tix * G_;
            float xr = gxr[j], xz = gxr[H_ + j], xn = gxr[2 * H_ + j];
            float hr = gh_s[(0 * 8 + jj) * 8 + b] + b_hh[j];
            float hz = gh_s[(1 * 8 + jj) * 8 + b] + b_hh[H_ + j];
            float hn = gh_s[(2 * 8 + jj) * 8 + b] + b_hh[2 * H_ + j];
            float r = 1.f / (1.f + __expf(-(xr + hr)));
            float z = 1.f / (1.f + __expf(-(xz + hz)));
            float n = tanhf(xn + r * hn);
            float hold = h_s[j * 8 + b];
            float hnew = (1.f - z) * n + z * hold;
            bool msk = (x[tix] == 0);            // PAD
            float hout = msk ? hold : hnew;
            g_hbuf[(p ^ 1) * H_ * B_ + j * 8 + b] = hout;
            g_feat[(size_t)tix * F_ + j] = msk ? 0.f : hout;
        }
        __threadfence();
        __syncthreads();
        if (tid == 0) {
            atomicAdd(&g_cnt[s], 1u);
            while (((volatile unsigned int*)g_cnt)[s] < gridDim.x) { }
        }
        __syncthreads();
    }
}

// ---------------- K6: combine per-tile softmax partials -> lse per row ----------------
__global__ void lse_kernel() {
    int row = blockIdx.x, lane = threadIdx.x;
    float m = -1e30f, s = 0.f;
    for (int i = lane; i < NT_; i += 32) {
        float2 p = g_part[(size_t)row * NT_ + i];
        if (p.x > m) { s = s * __expf(m - p.x) + p.y; m = p.x; }
        else         { s = s + p.y * __expf(p.x - m); }
    }
#pragma unroll
    for (int o = 16; o > 0; o >>= 1) {
        float mo = __shfl_xor_sync(0xffffffffu, m, o);
        float so = __shfl_xor_sync(0xffffffffu, s, o);
        if (mo > m) { s = s * __expf(m - mo) + so; m = mo; }
        else        { s = s + so * __expf(mo - m); }
    }
    if (lane == 0) g_lse[row] = m + logf(s);
}

// ---------------- K7: out = score - lse[row] ----------------
__global__ void sub_kernel(float* __restrict__ out) {
    size_t idx = (size_t)blockIdx.x * 256 + threadIdx.x;   // float4 index
    int row = (int)(idx / (V_ / 4));
    float4 v = ((float4*)out)[idx];
    float l = g_lse[row];
    v.x -= l; v.y -= l; v.z -= l; v.w -= l;
    ((float4*)out)[idx] = v;
}

// ---------------- launch ----------------
extern "C" void kernel_launch(void* const* d_in, const int* in_sizes, int n_in,
                              void* d_out, int out_size) {
    const int*   x     = (const int*)d_in[0];
    const float* emb_W = (const float*)d_in[1];
    const float* W_ih  = (const float*)d_in[2];
    const float* W_hh  = (const float*)d_in[3];
    const float* b_ih  = (const float*)d_in[4];
    const float* b_hh  = (const float*)d_in[5];
    const float* lin_W = (const float*)d_in[6];
    const float* lin_b = (const float*)d_in[7];
    float* out = (float*)d_out;

    float *feat, *gx, *logits;
    float2* part;
    cudaGetSymbolAddress((void**)&feat,   g_feat);
    cudaGetSymbolAddress((void**)&gx,     g_gx);
    cudaGetSymbolAddress((void**)&logits, g_logits);
    cudaGetSymbolAddress((void**)&part,   g_part);

    pack_kernel<<<GRU_CTAS, 256>>>(W_hh);
    embed_kernel<<<T_, 128>>>(x, emb_W);
    // gx = emb @ W_ih^T + b_ih   (A = feat[:, H:], lda = F)
    gemm_kernel<0><<<dim3(G_ / 128, T_ / 128), 256>>>(feat + H_, F_, W_ih, E_, b_ih,
                                                      gx, G_, E_, nullptr);
    gru_kernel<<<GRU_CTAS, 256>>>(x, b_hh);
    // logits = tanh(feat @ lin_W^T + lin_b)
    gemm_kernel<1><<<dim3(E_ / 128, T_ / 128), 256>>>(feat, F_, lin_W, F_, lin_b,
                                                      logits, E_, F_, nullptr);
    // scores = logits @ emb_W^T  (+ per-tile softmax partials)
    gemm_kernel<2><<<dim3(V_ / 128, T_ / 128), 256>>>(logits, E_, emb_W, E_, nullptr,
                                                      out, V_, E_, part);
    lse_kernel<<<T_, 32>>>();
    sub_kernel<<<(T_ * (V_ / 4)) / 256, 256>>>(out);
}

// round 4
// speedup vs baseline: 1.3773x; 1.3773x over previous
#include <cuda_runtime.h>
#include <cuda_bf16.h>
#include <math.h>
#include <cstdint>

#define B_ 8
#define S_ 256
#define V_ 32000
#define E_ 512
#define H_ 1024
#define G_ 3072      // 3H
#define T_ 2048      // B*S
#define F_ 1536      // H+E
#define NT_ 250      // V/128 score tiles per row (grid.x)
#define NT2_ 500     // per-row softmax partials (one per 64-wide half tile)
#define GRU_CTAS 128

// ---------------- scratch (static device globals; no allocation) ----------------
__device__ float g_Wpack[(size_t)GRU_CTAS * 1024 * 32];  // per-CTA packed W_hh [c][k][g24(pad32)]
__device__ float g_feat[(size_t)T_ * F_];                // [t][ ctx(1024) | emb(512) ]
__device__ float g_gx[(size_t)T_ * G_];                  // input gates
__device__ __nv_bfloat16 g_embh[(size_t)V_ * E_];        // emb table in bf16
__device__ __nv_bfloat16 g_logbf[(size_t)T_ * E_];       // logits in bf16
__device__ float2 g_part[(size_t)T_ * NT2_];             // per (row, half-tile): (max, sumexp)
__device__ float g_lse[T_];
__device__ float g_hbuf[2 * H_ * B_];                    // ping-pong hidden state [k][b]
__device__ unsigned int g_cnt[S_];                       // per-step barrier counters

// ---------------- K0: pack W_hh per GRU CTA + zero barrier counters ----------------
__global__ void pack_kernel(const float* __restrict__ W_hh) {
    int c = blockIdx.x, tid = threadIdx.x;
    if (c == 0 && tid < S_) g_cnt[tid] = 0u;
    for (int idx = tid; idx < 1024 * 32; idx += 256) {
        int k = idx >> 5, g24 = idx & 31;
        float v = 0.f;
        if (g24 < 24) {
            int gate = g24 >> 3, jj = g24 & 7;
            int g = gate * H_ + c * 8 + jj;
            v = W_hh[(size_t)g * H_ + k];
        }
        g_Wpack[(size_t)c * 32768 + idx] = v;
    }
}

// ---------------- K1: embedding gather into feat[:, H:] ----------------
__global__ void embed_kernel(const int* __restrict__ x, const float* __restrict__ emb_W) {
    int t = blockIdx.x, tid = threadIdx.x;
    int tok = x[t];
    const float4* src = (const float4*)(emb_W + (size_t)tok * E_);
    float4* dst = (float4*)(g_feat + (size_t)t * F_ + H_);
    dst[tid] = src[tid];
}

// ---------------- K2: fp32 -> bf16 convert (emb table) ----------------
__global__ void cvt_kernel(const float* __restrict__ src, __nv_bfloat16* __restrict__ dst) {
    int i = blockIdx.x * blockDim.x + threadIdx.x;   // float4 index
    float4 v = ((const float4*)src)[i];
    ((__nv_bfloat162*)dst)[2 * i]     = __floats2bfloat162_rn(v.x, v.y);
    ((__nv_bfloat162*)dst)[2 * i + 1] = __floats2bfloat162_rn(v.z, v.w);
}

// ---------------- fp32 SIMT GEMM C = A@B^T (128x128x16 tile) ----------------
// EPI 0: +bias -> fp32. EPI 1: tanh(+bias) -> bf16 (Cb).
template <int EPI>
__global__ void __launch_bounds__(256) gemm_kernel(
    const float* __restrict__ A, int lda,
    const float* __restrict__ Bm, int ldb,
    const float* __restrict__ bias,
    float* __restrict__ C, __nv_bfloat16* __restrict__ Cb, int ldc, int K)
{
    __shared__ float As[16 * 128];
    __shared__ float Bs[16 * 128];
    const int tid = threadIdx.x;
    const int tx = tid & 15, ty = tid >> 4;
    const int m0 = blockIdx.y * 128, n0 = blockIdx.x * 128;

    float acc[8][8];
#pragma unroll
    for (int i = 0; i < 8; ++i)
#pragma unroll
        for (int j = 0; j < 8; ++j) acc[i][j] = 0.f;

    for (int k0 = 0; k0 < K; k0 += 16) {
#pragma unroll
        for (int r = 0; r < 2; ++r) {
            int idx = tid + r * 256;
            int rr = idx >> 2, q = idx & 3;
            float4 va = *(const float4*)(A + (size_t)(m0 + rr) * lda + k0 + q * 4);
            As[(q * 4 + 0) * 128 + rr] = va.x;
            As[(q * 4 + 1) * 128 + rr] = va.y;
            As[(q * 4 + 2) * 128 + rr] = va.z;
            As[(q * 4 + 3) * 128 + rr] = va.w;
            float4 vb = *(const float4*)(Bm + (size_t)(n0 + rr) * ldb + k0 + q * 4);
            Bs[(q * 4 + 0) * 128 + rr] = vb.x;
            Bs[(q * 4 + 1) * 128 + rr] = vb.y;
            Bs[(q * 4 + 2) * 128 + rr] = vb.z;
            Bs[(q * 4 + 3) * 128 + rr] = vb.w;
        }
        __syncthreads();
#pragma unroll
        for (int kk = 0; kk < 16; ++kk) {
            float a[8], b[8];
            *(float4*)(a)     = *(const float4*)(As + kk * 128 + ty * 8);
            *(float4*)(a + 4) = *(const float4*)(As + kk * 128 + ty * 8 + 4);
            *(float4*)(b)     = *(const float4*)(Bs + kk * 128 + tx * 8);
            *(float4*)(b + 4) = *(const float4*)(Bs + kk * 128 + tx * 8 + 4);
#pragma unroll
            for (int i = 0; i < 8; ++i)
#pragma unroll
                for (int j = 0; j < 8; ++j) acc[i][j] += a[i] * b[j];
        }
        __syncthreads();
    }

    float bn[8];
#pragma unroll
    for (int j = 0; j < 8; ++j) bn[j] = bias[n0 + tx * 8 + j];
#pragma unroll
    for (int i = 0; i < 8; ++i) {
        int row = m0 + ty * 8 + i;
        if (EPI == 0) {
            float* cp = C + (size_t)row * ldc + n0 + tx * 8;
#pragma unroll
            for (int j4 = 0; j4 < 8; j4 += 4) {
                float4 v;
                v.x = acc[i][j4 + 0] + bn[j4 + 0];
                v.y = acc[i][j4 + 1] + bn[j4 + 1];
                v.z = acc[i][j4 + 2] + bn[j4 + 2];
                v.w = acc[i][j4 + 3] + bn[j4 + 3];
                *(float4*)(cp + j4) = v;
            }
        } else {
            float v[8];
#pragma unroll
            for (int j = 0; j < 8; ++j) v[j] = tanhf(acc[i][j] + bn[j]);
            __nv_bfloat162* cp = (__nv_bfloat162*)(Cb + (size_t)row * ldc + n0 + tx * 8);
            cp[0] = __floats2bfloat162_rn(v[0], v[1]);
            cp[1] = __floats2bfloat162_rn(v[2], v[3]);
            cp[2] = __floats2bfloat162_rn(v[4], v[5]);
            cp[3] = __floats2bfloat162_rn(v[6], v[7]);
        }
    }
}

// ---------------- K3: persistent GRU (unchanged this round) ----------------
__global__ void __launch_bounds__(256, 1) gru_kernel(const int* __restrict__ x,
                                                     const float* __restrict__ b_hh) {
    __shared__ float h_s[H_ * B_];
    __shared__ float red[24 * 8 * 8];
    __shared__ float gh_s[24 * 8];
    const int c = blockIdx.x, tid = threadIdx.x;
    const int j0 = c * 8;
    const int g24 = tid % 24, kc = tid / 24;

    for (int s = 0; s < S_; ++s) {
        const int p = s & 1;
        if (s == 0) {
            for (int i = tid; i < H_ * B_; i += 256) h_s[i] = 0.f;
        } else {
            const float4* src = (const float4*)(g_hbuf + p * H_ * B_);
            float4* dst = (float4*)h_s;
#pragma unroll
            for (int r = 0; r < 8; ++r) dst[tid + r * 256] = __ldcg(src + tid + r * 256);
        }
        __syncthreads();

        if (tid < 192) {
            float a0 = 0, a1 = 0, a2 = 0, a3 = 0, a4 = 0, a5 = 0, a6 = 0, a7 = 0;
            const float* wp = g_Wpack + ((size_t)c * 1024 + kc * 128) * 32 + g24;
            const float4* h4 = (const float4*)h_s + kc * 128 * 2;
#pragma unroll 4
            for (int k = 0; k < 128; ++k) {
                float w = wp[k * 32];
                float4 ha = h4[2 * k], hb = h4[2 * k + 1];
                a0 += w * ha.x; a1 += w * ha.y; a2 += w * ha.z; a3 += w * ha.w;
                a4 += w * hb.x; a5 += w * hb.y; a6 += w * hb.z; a7 += w * hb.w;
            }
            float* rp = red + (g24 * 8 + kc) * 8;
            rp[0] = a0; rp[1] = a1; rp[2] = a2; rp[3] = a3;
            rp[4] = a4; rp[5] = a5; rp[6] = a6; rp[7] = a7;
        }
        __syncthreads();
        if (tid < 192) {
            int gg = tid % 24, b = tid / 24;
            float v = 0.f;
#pragma unroll
            for (int q = 0; q < 8; ++q) v += red[(gg * 8 + q) * 8 + b];
            gh_s[gg * 8 + b] = v;
        }
        __syncthreads();
        if (tid < 64) {
            int jj = tid >> 3, b = tid & 7;
            int j = j0 + jj;
            int tix = b * S_ + s;
            const float* gxr = g_gx + (size_t)tix * G_;
            float xr = gxr[j], xz = gxr[H_ + j], xn = gxr[2 * H_ + j];
            float hr = gh_s[(0 * 8 + jj) * 8 + b] + b_hh[j];
            float hz = gh_s[(1 * 8 + jj) * 8 + b] + b_hh[H_ + j];
            float hn = gh_s[(2 * 8 + jj) * 8 + b] + b_hh[2 * H_ + j];
            float r = 1.f / (1.f + __expf(-(xr + hr)));
            float z = 1.f / (1.f + __expf(-(xz + hz)));
            float n = tanhf(xn + r * hn);
            float hold = h_s[j * 8 + b];
            float hnew = (1.f - z) * n + z * hold;
            bool msk = (x[tix] == 0);
            float hout = msk ? hold : hnew;
            g_hbuf[(p ^ 1) * H_ * B_ + j * 8 + b] = hout;
            g_feat[(size_t)tix * F_ + j] = msk ? 0.f : hout;
        }
        __threadfence();
        __syncthreads();
        if (tid == 0) {
            atomicAdd(&g_cnt[s], 1u);
            while (((volatile unsigned int*)g_cnt)[s] < gridDim.x) { }
        }
        __syncthreads();
    }
}

// ---------------- K5: HMMA bf16 scores GEMM + fused softmax partials ----------------
// scores = logits_bf16 @ emb_bf16^T, fp32 accum. CTA tile 128x128, warp tile 32x64.
// mma.sync.aligned.m16n8k16 (sm_80+, works on plain sm_103 target).
__device__ __forceinline__ void mma16816(float* c, const uint32_t* a, uint32_t b0, uint32_t b1) {
    asm volatile(
        "mma.sync.aligned.m16n8k16.row.col.f32.bf16.bf16.f32 "
        "{%0,%1,%2,%3}, {%4,%5,%6,%7}, {%8,%9}, {%0,%1,%2,%3};"
        : "+f"(c[0]), "+f"(c[1]), "+f"(c[2]), "+f"(c[3])
        : "r"(a[0]), "r"(a[1]), "r"(a[2]), "r"(a[3]), "r"(b0), "r"(b1));
}

#define LDP_ 72   // padded row length (bf16 elems): conflict-free quad access

__global__ void __launch_bounds__(256) scores_kernel(
    const __nv_bfloat16* __restrict__ Abf,   // [T][E]
    const __nv_bfloat16* __restrict__ Bbf,   // [V][E]
    float* __restrict__ out, float2* __restrict__ part)
{
    __shared__ __nv_bfloat16 As[128 * LDP_];
    __shared__ __nv_bfloat16 Bs[128 * LDP_];
    const int tid = threadIdx.x, wid = tid >> 5, lane = tid & 31;
    const int m0 = blockIdx.y * 128, n0 = blockIdx.x * 128;
    const int mi = wid >> 1, nj = wid & 1;    // warp grid 4 (m) x 2 (n)
    const int qr = lane >> 2, qc = lane & 3;  // quad row / col-in-quad

    float acc[2][8][4];
#pragma unroll
    for (int ms = 0; ms < 2; ++ms)
#pragma unroll
        for (int ns = 0; ns < 8; ++ns)
#pragma unroll
            for (int q = 0; q < 4; ++q) acc[ms][ns][q] = 0.f;

    for (int k0 = 0; k0 < E_; k0 += 64) {
#pragma unroll
        for (int i = 0; i < 4; ++i) {
            int u = tid + i * 256;
            int r = u >> 3, c = u & 7;             // 8 uint4 per 64-wide row
            *(uint4*)(As + r * LDP_ + c * 8) =
                *(const uint4*)(Abf + (size_t)(m0 + r) * E_ + k0 + c * 8);
            *(uint4*)(Bs + r * LDP_ + c * 8) =
                *(const uint4*)(Bbf + (size_t)(n0 + r) * E_ + k0 + c * 8);
        }
        __syncthreads();
#pragma unroll
        for (int kk = 0; kk < 64; kk += 16) {
            int ak = kk + qc * 2;
            uint32_t a[2][4];
#pragma unroll
            for (int ms = 0; ms < 2; ++ms) {
                const __nv_bfloat16* ap = As + (size_t)(mi * 32 + ms * 16 + qr) * LDP_ + ak;
                a[ms][0] = *(const uint32_t*)(ap);
                a[ms][1] = *(const uint32_t*)(ap + 8 * LDP_);
                a[ms][2] = *(const uint32_t*)(ap + 8);
                a[ms][3] = *(const uint32_t*)(ap + 8 * LDP_ + 8);
            }
#pragma unroll
            for (int ns = 0; ns < 8; ++ns) {
                const __nv_bfloat16* bp = Bs + (size_t)(nj * 64 + ns * 8 + qr) * LDP_ + ak;
                uint32_t b0 = *(const uint32_t*)(bp);
                uint32_t b1 = *(const uint32_t*)(bp + 8);
                mma16816(acc[0][ns], a[0], b0, b1);
                mma16816(acc[1][ns], a[1], b0, b1);
            }
        }
        __syncthreads();
    }

    // ---- epilogue: store + per-row (max, sumexp) over this warp's 64-wide slice ----
    const int colbase = n0 + nj * 64;
#pragma unroll
    for (int ms = 0; ms < 2; ++ms) {
#pragma unroll
        for (int half = 0; half < 2; ++half) {          // c[0..1] row qr, c[2..3] row qr+8
            int row = m0 + mi * 32 + ms * 16 + half * 8 + qr;
            // store this row's 16 values (8 n-subtiles x 2)
            float* op = out + (size_t)row * V_ + colbase + qc * 2;
            float mx = -1e30f;
#pragma unroll
            for (int ns = 0; ns < 8; ++ns) {
                float v0 = acc[ms][ns][half * 2 + 0];
                float v1 = acc[ms][ns][half * 2 + 1];
                *(float2*)(op + ns * 8) = make_float2(v0, v1);
                mx = fmaxf(mx, fmaxf(v0, v1));
            }
            // quad reduce max (lanes differ only in qc)
            mx = fmaxf(mx, __shfl_xor_sync(0xffffffffu, mx, 1));
            mx = fmaxf(mx, __shfl_xor_sync(0xffffffffu, mx, 2));
            float sm = 0.f;
#pragma unroll
            for (int ns = 0; ns < 8; ++ns) {
                sm += __expf(acc[ms][ns][half * 2 + 0] - mx);
                sm += __expf(acc[ms][ns][half * 2 + 1] - mx);
            }
            sm += __shfl_xor_sync(0xffffffffu, sm, 1);
            sm += __shfl_xor_sync(0xffffffffu, sm, 2);
            if (qc == 0)
                part[(size_t)row * NT2_ + blockIdx.x * 2 + nj] = make_float2(mx, sm);
        }
    }
}

// ---------------- K6: combine per-tile softmax partials -> lse per row ----------------
__global__ void lse_kernel() {
    int row = blockIdx.x, lane = threadIdx.x;
    float m = -1e30f, s = 0.f;
    for (int i = lane; i < NT2_; i += 32) {
        float2 p = g_part[(size_t)row * NT2_ + i];
        if (p.x > m) { s = s * __expf(m - p.x) + p.y; m = p.x; }
        else         { s = s + p.y * __expf(p.x - m); }
    }
#pragma unroll
    for (int o = 16; o > 0; o >>= 1) {
        float mo = __shfl_xor_sync(0xffffffffu, m, o);
        float so = __shfl_xor_sync(0xffffffffu, s, o);
        if (mo > m) { s = s * __expf(m - mo) + so; m = mo; }
        else        { s = s + so * __expf(mo - m); }
    }
    if (lane == 0) g_lse[row] = m + logf(s);
}

// ---------------- K7: out = score - lse[row] ----------------
__global__ void sub_kernel(float* __restrict__ out) {
    size_t idx = (size_t)blockIdx.x * 256 + threadIdx.x;
    int row = (int)(idx / (V_ / 4));
    float4 v = ((float4*)out)[idx];
    float l = g_lse[row];
    v.x -= l; v.y -= l; v.z -= l; v.w -= l;
    ((float4*)out)[idx] = v;
}

// ---------------- launch ----------------
extern "C" void kernel_launch(void* const* d_in, const int* in_sizes, int n_in,
                              void* d_out, int out_size) {
    const int*   x     = (const int*)d_in[0];
    const float* emb_W = (const float*)d_in[1];
    const float* W_ih  = (const float*)d_in[2];
    const float* W_hh  = (const float*)d_in[3];
    const float* b_ih  = (const float*)d_in[4];
    const float* b_hh  = (const float*)d_in[5];
    const float* lin_W = (const float*)d_in[6];
    const float* lin_b = (const float*)d_in[7];
    float* out = (float*)d_out;

    float *feat, *gx;
    __nv_bfloat16 *embh, *logbf;
    float2* part;
    cudaGetSymbolAddress((void**)&feat,  g_feat);
    cudaGetSymbolAddress((void**)&gx,    g_gx);
    cudaGetSymbolAddress((void**)&embh,  g_embh);
    cudaGetSymbolAddress((void**)&logbf, g_logbf);
    cudaGetSymbolAddress((void**)&part,  g_part);

    pack_kernel<<<GRU_CTAS, 256>>>(W_hh);
    embed_kernel<<<T_, 128>>>(x, emb_W);
    cvt_kernel<<<(V_ * E_ / 4) / 256, 256>>>(emb_W, embh);   // emb table -> bf16
    // gx = emb @ W_ih^T + b_ih
    gemm_kernel<0><<<dim3(G_ / 128, T_ / 128), 256>>>(feat + H_, F_, W_ih, E_, b_ih,
                                                      gx, nullptr, G_, E_);
    gru_kernel<<<GRU_CTAS, 256>>>(x, b_hh);
    // logits = tanh(feat @ lin_W^T + lin_b) -> bf16
    gemm_kernel<1><<<dim3(E_ / 128, T_ / 128), 256>>>(feat, F_, lin_W, F_, lin_b,
                                                      nullptr, logbf, E_, F_);
    // scores = logits_bf16 @ emb_bf16^T (HMMA) + fused partials
    scores_kernel<<<dim3(NT_, T_ / 128), 256>>>(logbf, embh, out, part);
    lse_kernel<<<T_, 32>>>();
    sub_kernel<<<(T_ * (V_ / 4)) / 256, 256>>>(out);
}

// round 5
// speedup vs baseline: 1.3798x; 1.0018x over previous
#include <cuda_runtime.h>
#include <cuda_bf16.h>
#include <math.h>
#include <cstdint>

#define B_ 8
#define S_ 256
#define V_ 32000
#define E_ 512
#define H_ 1024
#define G_ 3072      // 3H
#define T_ 2048      // B*S
#define F_ 1536      // H+E
#define NT_ 250      // V/128 score tiles per row (grid.x)
#define NT2_ 500     // per-row softmax partials (one per 64-wide half tile)
#define GRU_CTAS 128

// ---------------- scratch (static device globals; no allocation) ----------------
__device__ float g_Wpack[(size_t)GRU_CTAS * 1024 * 32];  // per-CTA packed W_hh [c][k][g24(pad32)]
__device__ float g_feat[(size_t)T_ * F_];                // [t][ ctx(1024) | emb(512) ]
__device__ float g_gx[(size_t)T_ * G_];                  // input gates
__device__ __nv_bfloat16 g_embh[(size_t)V_ * E_];        // emb table in bf16
__device__ __nv_bfloat16 g_logbf[(size_t)T_ * E_];       // logits in bf16
__device__ float2 g_part[(size_t)T_ * NT2_];             // per (row, half-tile): (max, sumexp)
__device__ float g_lse[T_];
__device__ float g_hbuf[2 * H_ * B_];                    // ping-pong hidden state [k][b]
__device__ unsigned int g_cnt[S_];                       // per-step barrier counters

// ---------------- packed f32x2 helpers (PTX ISA 8.6, sm_100 family) ----------------
__device__ __forceinline__ void fma2(uint64_t& c, uint64_t a, uint64_t b) {
    asm("fma.rn.f32x2 %0, %1, %2, %0;" : "+l"(c) : "l"(a), "l"(b));
}
__device__ __forceinline__ uint64_t pack_dup(float w) {
    uint64_t r;
    asm("mov.b64 %0, {%1, %1};" : "=l"(r) : "f"(w));
    return r;
}
__device__ __forceinline__ uint64_t pack2(float lo, float hi) {
    uint64_t r;
    asm("mov.b64 %0, {%1, %2};" : "=l"(r) : "f"(lo), "f"(hi));
    return r;
}
__device__ __forceinline__ void unpack2(uint64_t v, float& lo, float& hi) {
    asm("mov.b64 {%0, %1}, %2;" : "=f"(lo), "=f"(hi) : "l"(v));
}

// ---------------- K0: pack W_hh per GRU CTA + zero barrier counters ----------------
__global__ void pack_kernel(const float* __restrict__ W_hh) {
    int c = blockIdx.x, tid = threadIdx.x;
    if (c == 0 && tid < S_) g_cnt[tid] = 0u;
    for (int idx = tid; idx < 1024 * 32; idx += 256) {
        int k = idx >> 5, g24 = idx & 31;
        float v = 0.f;
        if (g24 < 24) {
            int gate = g24 >> 3, jj = g24 & 7;
            int g = gate * H_ + c * 8 + jj;
            v = W_hh[(size_t)g * H_ + k];
        }
        g_Wpack[(size_t)c * 32768 + idx] = v;
    }
}

// ---------------- K1: embedding gather into feat[:, H:] ----------------
__global__ void embed_kernel(const int* __restrict__ x, const float* __restrict__ emb_W) {
    int t = blockIdx.x, tid = threadIdx.x;
    int tok = x[t];
    const float4* src = (const float4*)(emb_W + (size_t)tok * E_);
    float4* dst = (float4*)(g_feat + (size_t)t * F_ + H_);
    dst[tid] = src[tid];
}

// ---------------- K2: fp32 -> bf16 convert (emb table) ----------------
__global__ void cvt_kernel(const float* __restrict__ src, __nv_bfloat16* __restrict__ dst) {
    int i = blockIdx.x * blockDim.x + threadIdx.x;   // float4 index
    float4 v = ((const float4*)src)[i];
    ((__nv_bfloat162*)dst)[2 * i]     = __floats2bfloat162_rn(v.x, v.y);
    ((__nv_bfloat162*)dst)[2 * i + 1] = __floats2bfloat162_rn(v.z, v.w);
}

// ---------------- fp32 SIMT GEMM C = A@B^T (128x128x16 tile, f32x2 core) ----------------
// EPI 0: +bias -> fp32. EPI 1: tanh(+bias) -> bf16 (Cb).
template <int EPI>
__global__ void __launch_bounds__(256) gemm_kernel(
    const float* __restrict__ A, int lda,
    const float* __restrict__ Bm, int ldb,
    const float* __restrict__ bias,
    float* __restrict__ C, __nv_bfloat16* __restrict__ Cb, int ldc, int K)
{
    __shared__ float As[16 * 128];
    __shared__ float Bs[16 * 128];
    const int tid = threadIdx.x;
    const int tx = tid & 15, ty = tid >> 4;
    const int m0 = blockIdx.y * 128, n0 = blockIdx.x * 128;

    uint64_t acc[8][4];
#pragma unroll
    for (int i = 0; i < 8; ++i)
#pragma unroll
        for (int j = 0; j < 4; ++j) acc[i][j] = 0ull;

    for (int k0 = 0; k0 < K; k0 += 16) {
#pragma unroll
        for (int r = 0; r < 2; ++r) {
            int idx = tid + r * 256;
            int rr = idx >> 2, q = idx & 3;
            float4 va = *(const float4*)(A + (size_t)(m0 + rr) * lda + k0 + q * 4);
            As[(q * 4 + 0) * 128 + rr] = va.x;
            As[(q * 4 + 1) * 128 + rr] = va.y;
            As[(q * 4 + 2) * 128 + rr] = va.z;
            As[(q * 4 + 3) * 128 + rr] = va.w;
            float4 vb = *(const float4*)(Bm + (size_t)(n0 + rr) * ldb + k0 + q * 4);
            Bs[(q * 4 + 0) * 128 + rr] = vb.x;
            Bs[(q * 4 + 1) * 128 + rr] = vb.y;
            Bs[(q * 4 + 2) * 128 + rr] = vb.z;
            Bs[(q * 4 + 3) * 128 + rr] = vb.w;
        }
        __syncthreads();
#pragma unroll
        for (int kk = 0; kk < 16; ++kk) {
            float a[8], b[8];
            *(float4*)(a)     = *(const float4*)(As + kk * 128 + ty * 8);
            *(float4*)(a + 4) = *(const float4*)(As + kk * 128 + ty * 8 + 4);
            *(float4*)(b)     = *(const float4*)(Bs + kk * 128 + tx * 8);
            *(float4*)(b + 4) = *(const float4*)(Bs + kk * 128 + tx * 8 + 4);
            uint64_t bb[4];
#pragma unroll
            for (int j = 0; j < 4; ++j) bb[j] = pack2(b[2 * j], b[2 * j + 1]);
#pragma unroll
            for (int i = 0; i < 8; ++i) {
                uint64_t aa = pack_dup(a[i]);
#pragma unroll
                for (int j = 0; j < 4; ++j) fma2(acc[i][j], aa, bb[j]);
            }
        }
        __syncthreads();
    }

    float bn[8];
#pragma unroll
    for (int j = 0; j < 8; ++j) bn[j] = bias[n0 + tx * 8 + j];
#pragma unroll
    for (int i = 0; i < 8; ++i) {
        int row = m0 + ty * 8 + i;
        float c8[8];
#pragma unroll
        for (int j = 0; j < 4; ++j) unpack2(acc[i][j], c8[2 * j], c8[2 * j + 1]);
        if (EPI == 0) {
            float* cp = C + (size_t)row * ldc + n0 + tx * 8;
#pragma unroll
            for (int j4 = 0; j4 < 8; j4 += 4) {
                float4 v;
                v.x = c8[j4 + 0] + bn[j4 + 0];
                v.y = c8[j4 + 1] + bn[j4 + 1];
                v.z = c8[j4 + 2] + bn[j4 + 2];
                v.w = c8[j4 + 3] + bn[j4 + 3];
                *(float4*)(cp + j4) = v;
            }
        } else {
            float v[8];
#pragma unroll
            for (int j = 0; j < 8; ++j) v[j] = tanhf(c8[j] + bn[j]);
            __nv_bfloat162* cp = (__nv_bfloat162*)(Cb + (size_t)row * ldc + n0 + tx * 8);
            cp[0] = __floats2bfloat162_rn(v[0], v[1]);
            cp[1] = __floats2bfloat162_rn(v[2], v[3]);
            cp[2] = __floats2bfloat162_rn(v[4], v[5]);
            cp[3] = __floats2bfloat162_rn(v[6], v[7]);
        }
    }
}

// ---------------- K3: persistent GRU v2 (f32x2 GEMV + cheap grid barrier) ----------------
__global__ void __launch_bounds__(256, 1) gru_kernel(const int* __restrict__ x,
                                                     const float* __restrict__ b_hh) {
    __shared__ float h_s[H_ * B_];        // [k][b]  32 KB
    __shared__ float red[24 * 8 * 8];     // [g24][kc][b]
    __shared__ float gh_s[24 * 8];        // [g24][b]
    const int c = blockIdx.x, tid = threadIdx.x;
    const int j0 = c * 8;
    const int g24 = tid % 24, kc = tid / 24;   // valid for tid < 192

    // gate-thread constants (tid < 64)
    const int jj = tid >> 3, bb = tid & 7;
    const int j = j0 + jj;
    float bh0 = 0.f, bh1 = 0.f, bh2 = 0.f;
    if (tid < 64) { bh0 = b_hh[j]; bh1 = b_hh[H_ + j]; bh2 = b_hh[2 * H_ + j]; }

    unsigned int* cnt;
    {
        unsigned int* base;
        asm("mov.u64 %0, g_cnt;" : "=l"(base));   // avoid generic-addr recompute
        cnt = base;
    }

    for (int s = 0; s < S_; ++s) {
        const int p = s & 1;

        // prefetch this step's gx / mask (gate threads) — hides 600cyc behind GEMV
        float xr = 0.f, xz = 0.f, xn = 0.f;
        int msk = 0, tix = 0;
        if (tid < 64) {
            tix = bb * S_ + s;
            const float* gxr = g_gx + (size_t)tix * G_;
            xr = __ldcg(gxr + j);
            xz = __ldcg(gxr + H_ + j);
            xn = __ldcg(gxr + 2 * H_ + j);
            msk = (__ldg(x + tix) == 0);           // PAD
        }

        if (s == 0) {
            for (int i = tid; i < H_ * B_; i += 256) h_s[i] = 0.f;
        } else {
            const float4* src = (const float4*)(g_hbuf + p * H_ * B_);
            float4* dst = (float4*)h_s;
#pragma unroll
            for (int r = 0; r < 8; ++r) dst[tid + r * 256] = __ldcg(src + tid + r * 256);
        }
        __syncthreads();

        if (tid < 192) {
            uint64_t a0 = 0ull, a1 = 0ull, a2 = 0ull, a3 = 0ull;
            const float* wp = g_Wpack + ((size_t)c * 1024 + kc * 128) * 32 + g24;
            const ulonglong2* h8 = (const ulonglong2*)h_s + kc * 128 * 2;  // 2 x (2 float2) per k
#pragma unroll 4
            for (int k = 0; k < 128; ++k) {
                uint64_t ww = pack_dup(wp[k * 32]);
                ulonglong2 u = h8[2 * k];
                ulonglong2 v = h8[2 * k + 1];
                fma2(a0, ww, u.x); fma2(a1, ww, u.y);
                fma2(a2, ww, v.x); fma2(a3, ww, v.y);
            }
            float* rp = red + (g24 * 8 + kc) * 8;
            unpack2(a0, rp[0], rp[1]);
            unpack2(a1, rp[2], rp[3]);
            unpack2(a2, rp[4], rp[5]);
            unpack2(a3, rp[6], rp[7]);
        }
        __syncthreads();
        if (tid < 192) {
            int gg = tid % 24, b = tid / 24;
            float v = 0.f;
#pragma unroll
            for (int q = 0; q < 8; ++q) v += red[(gg * 8 + q) * 8 + b];
            gh_s[gg * 8 + b] = v;
        }
        __syncthreads();
        if (tid < 64) {
            float hr = gh_s[(0 * 8 + jj) * 8 + bb] + bh0;
            float hz = gh_s[(1 * 8 + jj) * 8 + bb] + bh1;
            float hn = gh_s[(2 * 8 + jj) * 8 + bb] + bh2;
            float r = 1.f / (1.f + __expf(-(xr + hr)));
            float z = 1.f / (1.f + __expf(-(xz + hz)));
            float n = tanhf(xn + r * hn);
            float hold = h_s[j * 8 + bb];
            float hnew = (1.f - z) * n + z * hold;
            float hout = msk ? hold : hnew;
            g_hbuf[(p ^ 1) * H_ * B_ + j * 8 + bb] = hout;
            g_feat[(size_t)tix * F_ + j] = msk ? 0.f : hout;
        }
        if (s < S_ - 1) {
            __syncthreads();
            if (tid == 0) {
                // CG-style grid barrier: release-red + acquire-load poll (no atomic serialization stall)
                asm volatile("red.release.gpu.global.add.u32 [%0], 1;"
                             :: "l"(cnt + s) : "memory");
                unsigned int v;
                do {
                    asm volatile("ld.acquire.gpu.global.u32 %0, [%1];"
                                 : "=r"(v) : "l"(cnt + s) : "memory");
                } while (v < (unsigned)GRU_CTAS);
            }
            __syncthreads();
        }
    }
}

// ---------------- K5: HMMA bf16 scores GEMM + fused softmax partials ----------------
__device__ __forceinline__ void mma16816(float* c, const uint32_t* a, uint32_t b0, uint32_t b1) {
    asm volatile(
        "mma.sync.aligned.m16n8k16.row.col.f32.bf16.bf16.f32 "
        "{%0,%1,%2,%3}, {%4,%5,%6,%7}, {%8,%9}, {%0,%1,%2,%3};"
        : "+f"(c[0]), "+f"(c[1]), "+f"(c[2]), "+f"(c[3])
        : "r"(a[0]), "r"(a[1]), "r"(a[2]), "r"(a[3]), "r"(b0), "r"(b1));
}

#define LDP_ 72   // padded row length (bf16 elems): conflict-free quad access

__global__ void __launch_bounds__(256) scores_kernel(
    const __nv_bfloat16* __restrict__ Abf,   // [T][E]
    const __nv_bfloat16* __restrict__ Bbf,   // [V][E]
    float* __restrict__ out, float2* __restrict__ part)
{
    __shared__ __nv_bfloat16 As[128 * LDP_];
    __shared__ __nv_bfloat16 Bs[128 * LDP_];
    const int tid = threadIdx.x, wid = tid >> 5, lane = tid & 31;
    const int m0 = blockIdx.y * 128, n0 = blockIdx.x * 128;
    const int mi = wid >> 1, nj = wid & 1;    // warp grid 4 (m) x 2 (n)
    const int qr = lane >> 2, qc = lane & 3;  // quad row / col-in-quad

    float acc[2][8][4];
#pragma unroll
    for (int ms = 0; ms < 2; ++ms)
#pragma unroll
        for (int ns = 0; ns < 8; ++ns)
#pragma unroll
            for (int q = 0; q < 4; ++q) acc[ms][ns][q] = 0.f;

    for (int k0 = 0; k0 < E_; k0 += 64) {
#pragma unroll
        for (int i = 0; i < 4; ++i) {
            int u = tid + i * 256;
            int r = u >> 3, c = u & 7;             // 8 uint4 per 64-wide row
            *(uint4*)(As + r * LDP_ + c * 8) =
                *(const uint4*)(Abf + (size_t)(m0 + r) * E_ + k0 + c * 8);
            *(uint4*)(Bs + r * LDP_ + c * 8) =
                *(const uint4*)(Bbf + (size_t)(n0 + r) * E_ + k0 + c * 8);
        }
        __syncthreads();
#pragma unroll
        for (int kk = 0; kk < 64; kk += 16) {
            int ak = kk + qc * 2;
            uint32_t a[2][4];
#pragma unroll
            for (int ms = 0; ms < 2; ++ms) {
                const __nv_bfloat16* ap = As + (size_t)(mi * 32 + ms * 16 + qr) * LDP_ + ak;
                a[ms][0] = *(const uint32_t*)(ap);
                a[ms][1] = *(const uint32_t*)(ap + 8 * LDP_);
                a[ms][2] = *(const uint32_t*)(ap + 8);
                a[ms][3] = *(const uint32_t*)(ap + 8 * LDP_ + 8);
            }
#pragma unroll
            for (int ns = 0; ns < 8; ++ns) {
                const __nv_bfloat16* bp = Bs + (size_t)(nj * 64 + ns * 8 + qr) * LDP_ + ak;
                uint32_t b0 = *(const uint32_t*)(bp);
                uint32_t b1 = *(const uint32_t*)(bp + 8);
                mma16816(acc[0][ns], a[0], b0, b1);
                mma16816(acc[1][ns], a[1], b0, b1);
            }
        }
        __syncthreads();
    }

    // ---- epilogue: store + per-row (max, sumexp) over this warp's 64-wide slice ----
    const int colbase = n0 + nj * 64;
#pragma unroll
    for (int ms = 0; ms < 2; ++ms) {
#pragma unroll
        for (int half = 0; half < 2; ++half) {          // c[0..1] row qr, c[2..3] row qr+8
            int row = m0 + mi * 32 + ms * 16 + half * 8 + qr;
            float* op = out + (size_t)row * V_ + colbase + qc * 2;
            float mx = -1e30f;
#pragma unroll
            for (int ns = 0; ns < 8; ++ns) {
                float v0 = acc[ms][ns][half * 2 + 0];
                float v1 = acc[ms][ns][half * 2 + 1];
                *(float2*)(op + ns * 8) = make_float2(v0, v1);
                mx = fmaxf(mx, fmaxf(v0, v1));
            }
            mx = fmaxf(mx, __shfl_xor_sync(0xffffffffu, mx, 1));
            mx = fmaxf(mx, __shfl_xor_sync(0xffffffffu, mx, 2));
            float sm = 0.f;
#pragma unroll
            for (int ns = 0; ns < 8; ++ns) {
                sm += __expf(acc[ms][ns][half * 2 + 0] - mx);
                sm += __expf(acc[ms][ns][half * 2 + 1] - mx);
            }
            sm += __shfl_xor_sync(0xffffffffu, sm, 1);
            sm += __shfl_xor_sync(0xffffffffu, sm, 2);
            if (qc == 0)
                part[(size_t)row * NT2_ + blockIdx.x * 2 + nj] = make_float2(mx, sm);
        }
    }
}

// ---------------- K6: combine per-tile softmax partials -> lse per row ----------------
__global__ void lse_kernel() {
    int row = blockIdx.x, lane = threadIdx.x;
    float m = -1e30f, s = 0.f;
    for (int i = lane; i < NT2_; i += 32) {
        float2 p = g_part[(size_t)row * NT2_ + i];
        if (p.x > m) { s = s * __expf(m - p.x) + p.y; m = p.x; }
        else         { s = s + p.y * __expf(p.x - m); }
    }
#pragma unroll
    for (int o = 16; o > 0; o >>= 1) {
        float mo = __shfl_xor_sync(0xffffffffu, m, o);
        float so = __shfl_xor_sync(0xffffffffu, s, o);
        if (mo > m) { s = s * __expf(m - mo) + so; m = mo; }
        else        { s = s + so * __expf(mo - m); }
    }
    if (lane == 0) g_lse[row] = m + logf(s);
}

// ---------------- K7: out = score - lse[row] ----------------
__global__ void sub_kernel(float* __restrict__ out) {
    size_t idx = (size_t)blockIdx.x * 256 + threadIdx.x;
    int row = (int)(idx / (V_ / 4));
    float4 v = ((float4*)out)[idx];
    float l = g_lse[row];
    v.x -= l; v.y -= l; v.z -= l; v.w -= l;
    ((float4*)out)[idx] = v;
}

// ---------------- launch ----------------
extern "C" void kernel_launch(void* const* d_in, const int* in_sizes, int n_in,
                              void* d_out, int out_size) {
    const int*   x     = (const int*)d_in[0];
    const float* emb_W = (const float*)d_in[1];
    const float* W_ih  = (const float*)d_in[2];
    const float* W_hh  = (const float*)d_in[3];
    const float* b_ih  = (const float*)d_in[4];
    const float* b_hh  = (const float*)d_in[5];
    const float* lin_W = (const float*)d_in[6];
    const float* lin_b = (const float*)d_in[7];
    float* out = (float*)d_out;

    float *feat, *gx;
    __nv_bfloat16 *embh, *logbf;
    float2* part;
    cudaGetSymbolAddress((void**)&feat,  g_feat);
    cudaGetSymbolAddress((void**)&gx,    g_gx);
    cudaGetSymbolAddress((void**)&embh,  g_embh);
    cudaGetSymbolAddress((void**)&logbf, g_logbf);
    cudaGetSymbolAddress((void**)&part,  g_part);

    pack_kernel<<<GRU_CTAS, 256>>>(W_hh);
    embed_kernel<<<T_, 128>>>(x, emb_W);
    cvt_kernel<<<(V_ * E_ / 4) / 256, 256>>>(emb_W, embh);   // emb table -> bf16
    // gx = emb @ W_ih^T + b_ih
    gemm_kernel<0><<<dim3(G_ / 128, T_ / 128), 256>>>(feat + H_, F_, W_ih, E_, b_ih,
                                                      gx, nullptr, G_, E_);
    gru_kernel<<<GRU_CTAS, 256>>>(x, b_hh);
    // logits = tanh(feat @ lin_W^T + lin_b) -> bf16
    gemm_kernel<1><<<dim3(E_ / 128, T_ / 128), 256>>>(feat, F_, lin_W, F_, lin_b,
                                                      nullptr, logbf, E_, F_);
    // scores = logits_bf16 @ emb_bf16^T (HMMA) + fused partials
    scores_kernel<<<dim3(NT_, T_ / 128), 256>>>(logbf, embh, out, part);
    lse_kernel<<<T_, 32>>>();
    sub_kernel<<<(T_ * (V_ / 4)) / 256, 256>>>(out);
}